// round 16
// baseline (speedup 1.0000x reference)
#include <cuda_runtime.h>
#include <cuda_bf16.h>

#define L  48
#define NB 396     // 3 blocks/SM co-resident (396 <= 3*148) -> single wave

// ---- scratch (device globals; no allocations) ----
__device__ float g_qkp[2][L * 256];   // split-K partials: [0,128)=q, [128,256)=k
__device__ float g_rootp[2][L * 256]; // split-K partials of X @ W_root
__device__ float g_attn[L * L];
__device__ float g_h[L * 256];

// grid barrier (count returns to 0 each barrier; gen read-before-arrive)
__device__ int g_bar_count;
__device__ volatile int g_bar_gen;

// local t = sp_i*4 + sp_j*2 + dir  ->  global etype = 96*sp_i + 2*sp_j + dir
__constant__ int c_etype[8] = {0, 1, 2, 3, 96, 97, 98, 99};

__device__ __forceinline__ float ftanh(float x) {
    float y; asm("tanh.approx.f32 %0, %1;" : "=f"(y) : "f"(x)); return y;
}

__device__ __forceinline__ void gsync() {
    __syncthreads();
    if (threadIdx.x == 0) {
        __threadfence();                       // release
        int gen = g_bar_gen;                   // read BEFORE arriving
        if (atomicAdd(&g_bar_count, 1) == NB - 1) {
            g_bar_count = 0;
            __threadfence();
            g_bar_gen = gen + 1;
        } else {
            while (g_bar_gen == gen) { }
        }
        __threadfence();                       // acquire
    }
    __syncthreads();
}

__global__ void __launch_bounds__(256, 3)
fused(const float* __restrict__ X,      const int*   __restrict__ speaker,
      const float* __restrict__ Wq,     const float* __restrict__ Wk,
      const float* __restrict__ v,      const float* __restrict__ Wrel,
      const float* __restrict__ Wr,     const float* __restrict__ b_rgcn,
      const float* __restrict__ Wnbr,   const float* __restrict__ Wself,
      const float* __restrict__ bg,     float*       __restrict__ out) {
    __shared__ float smem[2304];               // 9 KB, re-carved per phase
    int bid = blockIdx.x, tid = threadIdx.x;

    // ===== P1: [q|k|root] = X @ [Wq|Wk|Wroot], split-K partials =============
    // 384 blocks: 12 rowtiles(4) x 16 colslices(32) x 2 k-outer(128).
    // Thread: 32 cols x 8 ki-chunks(16) -> 16 W loads, 4 rows.
    if (bid < 384) {
        int rt = bid >> 5, cs = (bid >> 1) & 15, ko = bid & 1;
        int r0 = rt * 4;
        float* xs  = smem;                     // [4][128]
        float* red = smem + 512;               // [7][4][32]
        for (int idx = tid; idx < 512; idx += 256) {
            int rr = idx >> 7, dd = idx & 127;
            xs[idx] = X[(r0 + rr) * 256 + ko * 128 + dd];
        }
        __syncthreads();
        int cl = tid & 31, ki = tid >> 5;      // ki in [0,8)
        int c  = cs * 32 + cl;
        const float* Wb; int stride;
        if (c < 128)      { Wb = Wq + c;         stride = 128; }
        else if (c < 256) { Wb = Wk + (c - 128); stride = 128; }
        else              { Wb = Wr + (c - 256); stride = 256; }
        Wb += (size_t)(ko * 128 + ki * 16) * stride;
        const float* xk = &xs[ki * 16];
        float a0 = 0.f, a1 = 0.f, a2 = 0.f, a3 = 0.f;
#pragma unroll
        for (int d = 0; d < 16; d++) {
            float w = Wb[(size_t)d * stride];
            a0 = fmaf(xk[d],       w, a0);
            a1 = fmaf(xk[128 + d], w, a1);
            a2 = fmaf(xk[256 + d], w, a2);
            a3 = fmaf(xk[384 + d], w, a3);
        }
        if (ki > 0) {
            float* r = &red[(ki - 1) * 128];
            r[0 * 32 + cl] = a0; r[1 * 32 + cl] = a1;
            r[2 * 32 + cl] = a2; r[3 * 32 + cl] = a3;
        }
        __syncthreads();
        if (ki == 0) {
#pragma unroll
            for (int p = 0; p < 7; p++) {
                const float* r = &red[p * 128];
                a0 += r[cl]; a1 += r[32 + cl]; a2 += r[64 + cl]; a3 += r[96 + cl];
            }
            float* dst = (c < 256) ? &g_qkp[ko][0] : &g_rootp[ko][0];
            int cc = (c < 256) ? c : (c - 256);
            dst[(r0 + 0) * 256 + cc] = a0;
            dst[(r0 + 1) * 256 + cc] = a1;
            dst[(r0 + 2) * 256 + cc] = a2;
            dst[(r0 + 3) * 256 + cc] = a3;
        }
    }
    gsync();

    // ===== P2: attention (0-47) + h init (48-95) + P4 X-preload (96-383) ===
    if (bid < 48) {
        float* qs  = smem;            // [0,128)
        float* vs  = smem + 128;      // [128,256)
        float* sc  = smem + 256;      // [256,304)
        float* sp4 = smem + 304;      // [304,496)
        float* se  = smem + 496;      // [496,544)
        int i = bid;
        if (tid < 128) {
            qs[tid] = g_qkp[0][i * 256 + tid] + g_qkp[1][i * 256 + tid];
            vs[tid] = v[tid];
        }
        __syncthreads();
        int s = tid >> 6, u = tid & 63;        // 4 a-chunks(32) x 48 keys
        float ps = 0.f;
        if (u < 48) {
            const float4* k0 = (const float4*)&g_qkp[0][u * 256 + 128 + s * 32];
            const float4* k1 = (const float4*)&g_qkp[1][u * 256 + 128 + s * 32];
            const float *qq = &qs[s * 32], *vv = &vs[s * 32];
#pragma unroll
            for (int a4 = 0; a4 < 8; a4++) {
                float4 x0 = k0[a4], x1 = k1[a4];
                int a = a4 * 4;
                ps += vv[a + 0] * ftanh(qq[a + 0] + x0.x + x1.x);
                ps += vv[a + 1] * ftanh(qq[a + 1] + x0.y + x1.y);
                ps += vv[a + 2] * ftanh(qq[a + 2] + x0.z + x1.z);
                ps += vv[a + 3] * ftanh(qq[a + 3] + x0.w + x1.w);
            }
            sp4[s * 48 + u] = ps;
        }
        __syncthreads();
        if (tid < 48)
            sc[tid] = sp4[tid] + sp4[48 + tid] + sp4[96 + tid] + sp4[144 + tid];
        __syncthreads();
        float e = 0.f;
        if (tid < 48) {
            float mx = sc[0];
#pragma unroll 8
            for (int j = 1; j < 48; j++) mx = fmaxf(mx, sc[j]);
            e = __expf(sc[tid] - mx);
            se[tid] = e;
        }
        __syncthreads();
        if (tid < 48) {
            float sum = 0.f;
#pragma unroll 8
            for (int j = 0; j < 48; j++) sum += se[j];
            g_attn[i * 48 + tid] = e / sum;
        }
    } else if (bid < 96) {
        int o = (bid - 48) * 256 + tid;        // h init = root + b_rgcn
        g_h[o] = g_rootp[0][o] + g_rootp[1][o] + b_rgcn[tid];
    } else if (bid < 384) {
        // preload this block's P4 X-tile + speakers (inputs; no dependency)
        int ks = (bid >> 3) & 15, d0 = ks * 16;
        float* xs = smem;                      // [48][16]
        for (int idx = tid; idx < 768; idx += 256) {
            int i = idx >> 4, dd = idx & 15;
            xs[idx] = X[i * 256 + d0 + dd];
        }
        if (tid < 48) ((int*)(smem + 1792))[tid] = speaker[tid];
    }
    gsync();

    // ===== P4: h += Z_t @ W_t, Z built inline ==============================
    // 384 blocks: 8 types x 16 ksplit(16) x 3 rowtiles(16).
    // Blocks 384-395: init out = b_gcn.
    if (bid < 384) {
        int t = bid & 7, ks = (bid >> 3) & 15, rt = bid >> 7;
        int tb   = (t >> 1) & 1;               // sp_j bit of this type
        int tsi  = t >> 2;                     // sp_i bit
        int dirb = t & 1;                      // direction bit
        int row0 = rt * 16, d0 = ks * 16;
        float* xs = smem;                      // [48][16]
        float* as = smem + 768;                // [48][16]
        float* zs = smem + 1536;               // [16][16]
        int*   sp = (int*)(smem + 1792);       // [48]
        if (bid < 96) {                        // not preloaded during P2
            for (int idx = tid; idx < 768; idx += 256) {
                int i = idx >> 4, dd = idx & 15;
                xs[idx] = X[i * 256 + d0 + dd];
            }
            if (tid < 48) sp[tid] = speaker[tid];
        }
        for (int idx = tid; idx < 768; idx += 256) {
            int i = idx >> 4, jj = idx & 15;
            as[idx] = g_attn[i * 48 + row0 + jj];
        }
        __syncthreads();

        // Z: 256 elements, 1/thread
        {
            int jj = tid >> 4, d = tid & 15;
            int j = row0 + jj;
            float acc = 0.f;
#pragma unroll 8
            for (int i = 0; i < 48; i++) {
                int dir = (i < j) ? 0 : 1;
                bool inc = (sp[i] == tsi) && (dir == dirb);
                acc += inc ? as[i * 16 + jj] * xs[i * 16 + d] : 0.f;
            }
            zs[jj * 16 + d] = acc;
        }
        __syncthreads();

        // GEMM: thread micro-tile 4 rows x 4 cols, K=16, float4 W loads
        int cq = (tid & 63) * 4, rg = tid >> 6;
        const float* W = Wrel + (size_t)c_etype[t] * 65536 + (size_t)d0 * 256 + cq;
        const float* z = &zs[rg * 4 * 16];
        float4 a0 = {0,0,0,0}, a1 = {0,0,0,0}, a2 = {0,0,0,0}, a3 = {0,0,0,0};
#pragma unroll
        for (int d = 0; d < 16; d++) {
            float4 w = *(const float4*)&W[(size_t)d * 256];
            float v0 = z[d], v1 = z[16 + d], v2 = z[32 + d], v3 = z[48 + d];
            a0.x = fmaf(v0, w.x, a0.x); a0.y = fmaf(v0, w.y, a0.y);
            a0.z = fmaf(v0, w.z, a0.z); a0.w = fmaf(v0, w.w, a0.w);
            a1.x = fmaf(v1, w.x, a1.x); a1.y = fmaf(v1, w.y, a1.y);
            a1.z = fmaf(v1, w.z, a1.z); a1.w = fmaf(v1, w.w, a1.w);
            a2.x = fmaf(v2, w.x, a2.x); a2.y = fmaf(v2, w.y, a2.y);
            a2.z = fmaf(v2, w.z, a2.z); a2.w = fmaf(v2, w.w, a2.w);
            a3.x = fmaf(v3, w.x, a3.x); a3.y = fmaf(v3, w.y, a3.y);
            a3.z = fmaf(v3, w.z, a3.z); a3.w = fmaf(v3, w.w, a3.w);
        }
        int lr = row0 + rg * 4;
        if (sp[lr + 0] == tb) {
            float* p = &g_h[(lr + 0) * 256 + cq];
            atomicAdd(p+0, a0.x); atomicAdd(p+1, a0.y);
            atomicAdd(p+2, a0.z); atomicAdd(p+3, a0.w);
        }
        if (sp[lr + 1] == tb) {
            float* p = &g_h[(lr + 1) * 256 + cq];
            atomicAdd(p+0, a1.x); atomicAdd(p+1, a1.y);
            atomicAdd(p+2, a1.z); atomicAdd(p+3, a1.w);
        }
        if (sp[lr + 2] == tb) {
            float* p = &g_h[(lr + 2) * 256 + cq];
            atomicAdd(p+0, a2.x); atomicAdd(p+1, a2.y);
            atomicAdd(p+2, a2.z); atomicAdd(p+3, a2.w);
        }
        if (sp[lr + 3] == tb) {
            float* p = &g_h[(lr + 3) * 256 + cq];
            atomicAdd(p+0, a3.x); atomicAdd(p+1, a3.y);
            atomicAdd(p+2, a3.z); atomicAdd(p+3, a3.w);
        }
    } else {
        int base = (bid - 384) * 1024;         // init out = bias (12 x 1024)
        float b = bg[tid];
#pragma unroll
        for (int k = 0; k < 4; k++)
            out[base + k * 256 + tid] = b;
    }
    gsync();

    // ===== P5: out += h @ W_self (k-split REDG)  +  broadcast T ============
    // 384 blocks: 24 rowpairs x 4 colslices(64) x 4 ksplit(64); inner ki(16).
    if (bid < 384) {
        int rt = bid >> 4, cs = (bid >> 2) & 3, ks = bid & 3;
        int j0 = rt * 2;
        float* hs  = smem;                     // [2][64]
        float* red = smem + 128;               // [3][64][2]
        if (tid < 128) {
            int rr = tid >> 6, dd = tid & 63;
            hs[tid] = g_h[(j0 + rr) * 256 + ks * 64 + dd];
        }
        __syncthreads();
        int cl = tid & 63, ki = tid >> 6;
        int c  = cs * 64 + cl;
        const float* Wb = Wself + (size_t)(ks * 64 + ki * 16) * 256 + c;
        const float *h0 = &hs[ki * 16], *h1 = &hs[64 + ki * 16];
        float a0 = 0.f, a1 = 0.f;
#pragma unroll
        for (int d = 0; d < 16; d++) {
            float w = Wb[(size_t)d * 256];
            a0 = fmaf(h0[d], w, a0);
            a1 = fmaf(h1[d], w, a1);
        }
        if (ki > 0) {
            float* r = &red[(ki - 1) * 128 + cl * 2];
            r[0] = a0; r[1] = a1;
        }
        __syncthreads();
        if (ki == 0) {
            const float *r1 = &red[cl * 2], *r2 = &red[128 + cl * 2], *r3 = &red[256 + cl * 2];
            atomicAdd(&out[j0 * 256 + c],       a0 + r1[0] + r2[0] + r3[0]);
            atomicAdd(&out[(j0 + 1) * 256 + c], a1 + r1[1] + r2[1] + r3[1]);
        }
    } else if (bid < 388) {
        // blocks 384..387: T k-chunk partial, scatter-added to all 48 rows
        int b = bid - 384;
        float* Ssc = smem;                     // [4][64]
        float* Sc  = smem + 256;               // [64]
        int dd = tid & 63, jg = tid >> 6;
        float s = 0.f;
#pragma unroll
        for (int j = jg * 12; j < jg * 12 + 12; j++)
            s += g_h[j * 256 + b * 64 + dd];
        Ssc[jg * 64 + dd] = s;
        __syncthreads();
        if (tid < 64) Sc[tid] = Ssc[tid] + Ssc[64 + tid] + Ssc[128 + tid] + Ssc[192 + tid];
        __syncthreads();
        float t = 0.f;
#pragma unroll 8
        for (int d = 0; d < 64; d++)
            t = fmaf(Sc[d], Wnbr[(size_t)(b * 64 + d) * 256 + tid], t);
#pragma unroll 8
        for (int j = 0; j < 48; j++)
            atomicAdd(&out[j * 256 + tid], t);
    }
}

extern "C" void kernel_launch(void* const* d_in, const int* in_sizes, int n_in,
                              void* d_out, int out_size) {
    const float* X      = (const float*)d_in[0];
    const int*   spk    = (const int*)  d_in[1];
    const float* Wq     = (const float*)d_in[2];
    const float* Wk     = (const float*)d_in[3];
    const float* v      = (const float*)d_in[4];
    const float* Wrel   = (const float*)d_in[5];
    const float* Wroot  = (const float*)d_in[6];
    const float* b_rgcn = (const float*)d_in[7];
    const float* Wnbr   = (const float*)d_in[8];
    const float* Wself  = (const float*)d_in[9];
    const float* b_gcn  = (const float*)d_in[10];
    float* out = (float*)d_out;

    fused<<<NB, 256>>>(X, spk, Wq, Wk, v, Wrel, Wroot, b_rgcn, Wnbr, Wself,
                       b_gcn, out);
}

// round 17
// speedup vs baseline: 1.0155x; 1.0155x over previous
#include <cuda_runtime.h>
#include <cuda_bf16.h>

#define L  48
#define NB 396     // 3 blocks/SM co-resident (396 <= 3*148) -> single wave
#define NBUCKET 12
#define BUCKET  33 // 12 * 33 = 396

// ---- scratch (device globals; no allocations) ----
__device__ float g_qkp[2][L * 256];   // split-K partials: [0,128)=q, [128,256)=k
__device__ float g_rootp[2][L * 256]; // split-K partials of X @ W_root
__device__ float g_attn[L * L];
__device__ float g_h[L * 256];

// 2-level tree barrier: 12 bucket counters (128B apart -> distinct LTS
// partitions, parallel arrival streams) + 1 root counter + generation flag.
// Counters return to 0 each barrier; gen is read-before-arrive, so the
// construct is correct across graph replays.
__device__ int g_cnt1[NBUCKET * 32];  // use [b*32], 128B stride
__device__ int g_cnt2;
__device__ volatile int g_bar_gen;

// local t = sp_i*4 + sp_j*2 + dir  ->  global etype = 96*sp_i + 2*sp_j + dir
__constant__ int c_etype[8] = {0, 1, 2, 3, 96, 97, 98, 99};

__device__ __forceinline__ float ftanh(float x) {
    float y; asm("tanh.approx.f32 %0, %1;" : "=f"(y) : "f"(x)); return y;
}

__device__ __forceinline__ void gsync(int bid) {
    __syncthreads();
    if (threadIdx.x == 0) {
        __threadfence();                        // release prior writes
        int gen = g_bar_gen;                    // read BEFORE arriving
        int b = bid / BUCKET;
        if (atomicAdd(&g_cnt1[b * 32], 1) == BUCKET - 1) {
            g_cnt1[b * 32] = 0;                 // safe: untouched until next gen
            if (atomicAdd(&g_cnt2, 1) == NBUCKET - 1) {
                g_cnt2 = 0;
                __threadfence();                // resets visible before flip
                g_bar_gen = gen + 1;
            }
        }
        while (g_bar_gen == gen) { }
        __threadfence();                        // acquire
    }
    __syncthreads();
}

__global__ void __launch_bounds__(256, 3)
fused(const float* __restrict__ X,      const int*   __restrict__ speaker,
      const float* __restrict__ Wq,     const float* __restrict__ Wk,
      const float* __restrict__ v,      const float* __restrict__ Wrel,
      const float* __restrict__ Wr,     const float* __restrict__ b_rgcn,
      const float* __restrict__ Wnbr,   const float* __restrict__ Wself,
      const float* __restrict__ bg,     float*       __restrict__ out) {
    __shared__ float smem[2304];               // 9 KB, re-carved per phase
    int bid = blockIdx.x, tid = threadIdx.x;

    // ===== P1: [q|k|root] = X @ [Wq|Wk|Wroot], split-K partials =============
    // 384 blocks: 12 rowtiles(4) x 16 colslices(32) x 2 k-outer(128).
    // Thread: 32 cols x 8 ki-chunks(16) -> 16 W loads, 4 rows.
    if (bid < 384) {
        int rt = bid >> 5, cs = (bid >> 1) & 15, ko = bid & 1;
        int r0 = rt * 4;
        float* xs  = smem;                     // [4][128]
        float* red = smem + 512;               // [7][4][32]
        for (int idx = tid; idx < 512; idx += 256) {
            int rr = idx >> 7, dd = idx & 127;
            xs[idx] = X[(r0 + rr) * 256 + ko * 128 + dd];
        }
        __syncthreads();
        int cl = tid & 31, ki = tid >> 5;      // ki in [0,8)
        int c  = cs * 32 + cl;
        const float* Wb; int stride;
        if (c < 128)      { Wb = Wq + c;         stride = 128; }
        else if (c < 256) { Wb = Wk + (c - 128); stride = 128; }
        else              { Wb = Wr + (c - 256); stride = 256; }
        Wb += (size_t)(ko * 128 + ki * 16) * stride;
        const float* xk = &xs[ki * 16];
        float a0 = 0.f, a1 = 0.f, a2 = 0.f, a3 = 0.f;
#pragma unroll
        for (int d = 0; d < 16; d++) {
            float w = Wb[(size_t)d * stride];
            a0 = fmaf(xk[d],       w, a0);
            a1 = fmaf(xk[128 + d], w, a1);
            a2 = fmaf(xk[256 + d], w, a2);
            a3 = fmaf(xk[384 + d], w, a3);
        }
        if (ki > 0) {
            float* r = &red[(ki - 1) * 128];
            r[0 * 32 + cl] = a0; r[1 * 32 + cl] = a1;
            r[2 * 32 + cl] = a2; r[3 * 32 + cl] = a3;
        }
        __syncthreads();
        if (ki == 0) {
#pragma unroll
            for (int p = 0; p < 7; p++) {
                const float* r = &red[p * 128];
                a0 += r[cl]; a1 += r[32 + cl]; a2 += r[64 + cl]; a3 += r[96 + cl];
            }
            float* dst = (c < 256) ? &g_qkp[ko][0] : &g_rootp[ko][0];
            int cc = (c < 256) ? c : (c - 256);
            dst[(r0 + 0) * 256 + cc] = a0;
            dst[(r0 + 1) * 256 + cc] = a1;
            dst[(r0 + 2) * 256 + cc] = a2;
            dst[(r0 + 3) * 256 + cc] = a3;
        }
    }
    gsync(bid);

    // ===== P2: attention (0-47) + h init (48-95) + P4 X-preload (96-383) ===
    if (bid < 48) {
        float* qs  = smem;            // [0,128)
        float* vs  = smem + 128;      // [128,256)
        float* sc  = smem + 256;      // [256,304)
        float* sp4 = smem + 304;      // [304,496)
        float* se  = smem + 496;      // [496,544)
        int i = bid;
        if (tid < 128) {
            qs[tid] = g_qkp[0][i * 256 + tid] + g_qkp[1][i * 256 + tid];
            vs[tid] = v[tid];
        }
        __syncthreads();
        int s = tid >> 6, u = tid & 63;        // 4 a-chunks(32) x 48 keys
        float ps = 0.f;
        if (u < 48) {
            const float4* k0 = (const float4*)&g_qkp[0][u * 256 + 128 + s * 32];
            const float4* k1 = (const float4*)&g_qkp[1][u * 256 + 128 + s * 32];
            const float *qq = &qs[s * 32], *vv = &vs[s * 32];
#pragma unroll
            for (int a4 = 0; a4 < 8; a4++) {
                float4 x0 = k0[a4], x1 = k1[a4];
                int a = a4 * 4;
                ps += vv[a + 0] * ftanh(qq[a + 0] + x0.x + x1.x);
                ps += vv[a + 1] * ftanh(qq[a + 1] + x0.y + x1.y);
                ps += vv[a + 2] * ftanh(qq[a + 2] + x0.z + x1.z);
                ps += vv[a + 3] * ftanh(qq[a + 3] + x0.w + x1.w);
            }
            sp4[s * 48 + u] = ps;
        }
        __syncthreads();
        if (tid < 48)
            sc[tid] = sp4[tid] + sp4[48 + tid] + sp4[96 + tid] + sp4[144 + tid];
        __syncthreads();
        float e = 0.f;
        if (tid < 48) {
            float mx = sc[0];
#pragma unroll 8
            for (int j = 1; j < 48; j++) mx = fmaxf(mx, sc[j]);
            e = __expf(sc[tid] - mx);
            se[tid] = e;
        }
        __syncthreads();
        if (tid < 48) {
            float sum = 0.f;
#pragma unroll 8
            for (int j = 0; j < 48; j++) sum += se[j];
            g_attn[i * 48 + tid] = e / sum;
        }
    } else if (bid < 96) {
        int o = (bid - 48) * 256 + tid;        // h init = root + b_rgcn
        g_h[o] = g_rootp[0][o] + g_rootp[1][o] + b_rgcn[tid];
    } else if (bid < 384) {
        // preload this block's P4 X-tile + speakers (inputs; no dependency)
        int ks = (bid >> 3) & 7, d0 = ks * 32;
        float* xs = smem;                      // [48][32]
        for (int idx = tid; idx < 1536; idx += 256) {
            int i = idx >> 5, dd = idx & 31;
            xs[idx] = X[i * 256 + d0 + dd];
        }
        if (tid < 48) ((int*)(smem + 2176))[tid] = speaker[tid];
    }
    gsync(bid);

    // ===== P4: h += Z_t @ W_t, Z built inline ==============================
    // 384 blocks: 8 types x 8 ksplit(32) x 6 rowtiles(8).
    // Blocks 384-395: init out = b_gcn.
    if (bid < 384) {
        int t = bid & 7, ks = (bid >> 3) & 7, rt = bid >> 6;
        int tb   = (t >> 1) & 1;               // sp_j bit of this type
        int tsi  = t >> 2;                     // sp_i bit
        int dirb = t & 1;                      // direction bit
        int row0 = rt * 8, d0 = ks * 32;
        float* xs = smem;                      // [48][32]
        float* as = smem + 1536;               // [48][8]
        float* zs = smem + 1920;               // [8][32]
        int*   sp = (int*)(smem + 2176);       // [48]
        if (bid < 96) {                        // not preloaded during P2
            for (int idx = tid; idx < 1536; idx += 256) {
                int i = idx >> 5, dd = idx & 31;
                xs[idx] = X[i * 256 + d0 + dd];
            }
            if (tid < 48) sp[tid] = speaker[tid];
        }
        for (int idx = tid; idx < 384; idx += 256) {
            int i = idx >> 3, jj = idx & 7;
            as[idx] = g_attn[i * 48 + row0 + jj];
        }
        __syncthreads();

        // Z: 256 elements, 1/thread
        {
            int jj = tid >> 5, d = tid & 31;
            int j = row0 + jj;
            float acc = 0.f;
#pragma unroll 8
            for (int i = 0; i < 48; i++) {
                int dir = (i < j) ? 0 : 1;
                bool inc = (sp[i] == tsi) && (dir == dirb);
                acc += inc ? as[i * 8 + jj] * xs[i * 32 + d] : 0.f;
            }
            zs[jj * 32 + d] = acc;
        }
        __syncthreads();

        // GEMM: thread micro-tile 2 rows x 4 cols, K=32, float4 W loads
        int cq = (tid & 63) * 4, rg = tid >> 6;
        const float* W = Wrel + (size_t)c_etype[t] * 65536 + (size_t)d0 * 256 + cq;
        const float* z = &zs[rg * 2 * 32];
        float4 a0 = {0,0,0,0}, a1 = {0,0,0,0};
#pragma unroll 8
        for (int d = 0; d < 32; d++) {
            float4 w = *(const float4*)&W[(size_t)d * 256];
            float v0 = z[d], v1 = z[32 + d];
            a0.x = fmaf(v0, w.x, a0.x); a0.y = fmaf(v0, w.y, a0.y);
            a0.z = fmaf(v0, w.z, a0.z); a0.w = fmaf(v0, w.w, a0.w);
            a1.x = fmaf(v1, w.x, a1.x); a1.y = fmaf(v1, w.y, a1.y);
            a1.z = fmaf(v1, w.z, a1.z); a1.w = fmaf(v1, w.w, a1.w);
        }
        int lr = row0 + rg * 2;
        if (sp[lr + 0] == tb) {
            float* p = &g_h[(lr + 0) * 256 + cq];
            atomicAdd(p+0, a0.x); atomicAdd(p+1, a0.y);
            atomicAdd(p+2, a0.z); atomicAdd(p+3, a0.w);
        }
        if (sp[lr + 1] == tb) {
            float* p = &g_h[(lr + 1) * 256 + cq];
            atomicAdd(p+0, a1.x); atomicAdd(p+1, a1.y);
            atomicAdd(p+2, a1.z); atomicAdd(p+3, a1.w);
        }
    } else {
        int base = (bid - 384) * 1024;         // init out = bias (12 x 1024)
        float b = bg[tid];
#pragma unroll
        for (int k = 0; k < 4; k++)
            out[base + k * 256 + tid] = b;
    }
    gsync(bid);

    // ===== P5: out += h @ W_self (k-split REDG)  +  broadcast T ============
    // 384 blocks: 48 rows x 2 colhalves(128) x 4 ksplit(64); inner ki(32).
    if (bid < 384) {
        int rt = bid >> 3, cs = (bid >> 2) & 1, ks = bid & 3;
        float* hs  = smem;                     // [64]
        float* red = smem + 64;                // [128]
        if (tid < 64) hs[tid] = g_h[rt * 256 + ks * 64 + tid];
        __syncthreads();
        int cl = tid & 127, ki = tid >> 7;
        int c  = cs * 128 + cl;
        const float* Wb = Wself + (size_t)(ks * 64 + ki * 32) * 256 + c;
        const float* h0 = &hs[ki * 32];
        float a0 = 0.f;
#pragma unroll 8
        for (int d = 0; d < 32; d++)
            a0 = fmaf(h0[d], Wb[(size_t)d * 256], a0);
        if (ki == 1) red[cl] = a0;
        __syncthreads();
        if (ki == 0)
            atomicAdd(&out[rt * 256 + c], a0 + red[cl]);
    } else if (bid < 388) {
        // blocks 384..387: T k-chunk partial, scatter-added to all 48 rows
        int b = bid - 384;
        float* Ssc = smem;                     // [4][64]
        float* Sc  = smem + 256;               // [64]
        int dd = tid & 63, jg = tid >> 6;
        float s = 0.f;
#pragma unroll
        for (int j = jg * 12; j < jg * 12 + 12; j++)
            s += g_h[j * 256 + b * 64 + dd];
        Ssc[jg * 64 + dd] = s;
        __syncthreads();
        if (tid < 64) Sc[tid] = Ssc[tid] + Ssc[64 + tid] + Ssc[128 + tid] + Ssc[192 + tid];
        __syncthreads();
        float t = 0.f;
#pragma unroll 8
        for (int d = 0; d < 64; d++)
            t = fmaf(Sc[d], Wnbr[(size_t)(b * 64 + d) * 256 + tid], t);
#pragma unroll 8
        for (int j = 0; j < 48; j++)
            atomicAdd(&out[j * 256 + tid], t);
    }
}

extern "C" void kernel_launch(void* const* d_in, const int* in_sizes, int n_in,
                              void* d_out, int out_size) {
    const float* X      = (const float*)d_in[0];
    const int*   spk    = (const int*)  d_in[1];
    const float* Wq     = (const float*)d_in[2];
    const float* Wk     = (const float*)d_in[3];
    const float* v      = (const float*)d_in[4];
    const float* Wrel   = (const float*)d_in[5];
    const float* Wroot  = (const float*)d_in[6];
    const float* b_rgcn = (const float*)d_in[7];
    const float* Wnbr   = (const float*)d_in[8];
    const float* Wself  = (const float*)d_in[9];
    const float* b_gcn  = (const float*)d_in[10];
    float* out = (float*)d_out;

    fused<<<NB, 256>>>(X, spk, Wq, Wk, v, Wrel, Wroot, b_rgcn, Wnbr, Wself,
                       b_gcn, out);
}